// round 5
// baseline (speedup 1.0000x reference)
#include <cuda_runtime.h>
#include <cstdint>

#define BB 32
#define SQ 128
#define EE 512
#define FF 2048

__device__ float g_H[(size_t)SQ * BB * FF];   // [s][b][f]
__device__ float g_Xr[(size_t)BB * SQ * EE];  // tf32-rounded x, [b][s][e]

__device__ __forceinline__ uint32_t smem_u32(const void* p) {
    uint32_t a;
    asm("{ .reg .u64 t; cvta.to.shared.u64 t, %1; cvt.u32.u64 %0, t; }" : "=r"(a) : "l"(p));
    return a;
}
#define MBAR_WAIT(m, ph) do {                                                  \
    asm volatile("{\n\t.reg .pred P1;\n\t"                                     \
        "W_%=:\n\t"                                                            \
        "mbarrier.try_wait.parity.shared.b64 P1, [%0], %1;\n\t"                \
        "@P1 bra.uni D_%=;\n\t"                                                \
        "bra.uni W_%=;\n\t"                                                    \
        "D_%=:\n\t}" :: "r"(m), "r"(ph) : "memory");                           \
} while (0)

__device__ __forceinline__ void bulk_cp(uint32_t dst, const void* src, uint32_t n,
                                        uint32_t mbar) {
    asm volatile(
        "cp.async.bulk.shared::cluster.global.mbarrier::complete_tx::bytes [%0], [%1], %2, [%3];"
        :: "r"(dst), "l"(src), "r"(n), "r"(mbar) : "memory");
}
__device__ __forceinline__ float rna(float v) {
    uint32_t r;
    asm("cvt.rna.tf32.f32 %0, %1;" : "=r"(r) : "f"(v));
    return __uint_as_float(r);
}
__device__ __forceinline__ uint32_t lds32(uint32_t a) {
    uint32_t v;
    asm volatile("ld.shared.b32 %0, [%1];" : "=r"(v) : "r"(a));
    return v;
}
__device__ __forceinline__ void mma8(float* c, const uint32_t* a, const uint32_t* b) {
    asm volatile(
        "mma.sync.aligned.m16n8k8.row.col.f32.tf32.tf32.f32 "
        "{%0,%1,%2,%3}, {%4,%5,%6,%7}, {%8,%9}, {%0,%1,%2,%3};"
        : "+f"(c[0]), "+f"(c[1]), "+f"(c[2]), "+f"(c[3])
        : "r"(a[0]), "r"(a[1]), "r"(a[2]), "r"(a[3]), "r"(b[0]), "r"(b[1]));
}

// Stage: A 32 rows x 144B (m-major, 128B data + 16B pad) = 4608B; B 32 k-rows x 512B = 16KB.
#define STG   20992
#define NS    4
#define OFF_M (NS * STG)
#define SMB   (OFF_M + 64)

// G==1: H[s][b][f] = Xr[:,s,:] @ W1[s] + b1[s]      (M=32,N=2048,K=512)
// G==2: out[b][s][e] = H[s] @ W2[s] + b2[s] + x     (M=32,N=512, K=2048)
template <int G>
__global__ __launch_bounds__(288) void ffn_mma(
    const float* __restrict__ Wt, const float* __restrict__ bias,
    const float* __restrict__ resid, float* __restrict__ outp)
{
    constexpr int K    = (G == 1) ? EE : FF;
    constexpr int NSTR = (G == 1) ? FF : EE;
    constexpr int NC   = K / 32;

    extern __shared__ char smem[];
    const uint32_t sb = smem_u32(smem);
    const int tid = threadIdx.x, wid = tid >> 5, lid = tid & 31;
    const int s = blockIdx.y, n0 = blockIdx.x * 128;
    const uint32_t g = lid >> 2, tig = lid & 3;

    if (tid == 0) {
#pragma unroll
        for (int i = 0; i < NS; i++) {
            asm volatile("mbarrier.init.shared.b64 [%0], 1;"
                         :: "r"(sb + OFF_M + i * 8) : "memory");       // full
            asm volatile("mbarrier.init.shared.b64 [%0], 8;"
                         :: "r"(sb + OFF_M + 32 + i * 8) : "memory");  // done
        }
    }
    __syncthreads();

    const float* Ab = (G == 1) ? g_Xr + (size_t)s * EE : g_H + (size_t)s * BB * FF;
    const size_t Ar = (G == 1) ? (size_t)SQ * EE : (size_t)FF;
    const float* Wb = Wt + (size_t)s * ((size_t)EE * FF) + n0;

    if (wid == 8) {
        // ---------------- producer ----------------
        for (int c = 0; c < NC; c++) {
            const int st = c & 3, k0 = c * 32;
            if (lid == 0) {
                if (c >= NS) MBAR_WAIT(sb + OFF_M + 32 + st * 8, ((c >> 2) - 1) & 1);
                asm volatile("mbarrier.arrive.expect_tx.shared.b64 _, [%0], %1;"
                             :: "r"(sb + OFF_M + st * 8), "r"(20480u) : "memory");
            }
            __syncwarp();
            if (lid < 8) {
                const uint32_t mb = sb + OFF_M + st * 8;
                const uint32_t rot = (lid & 3) * 32;  // bytes
#pragma unroll
                for (int j = 0; j < 4; j++) {
                    const int m = lid + 8 * j;
                    bulk_cp(sb + st * STG + m * 144, Ab + (size_t)m * Ar + k0, 128, mb);
                    const char* srcB =
                        (const char*)(Wb + (size_t)(k0 + m) * NSTR);
                    const uint32_t db = sb + st * STG + 4608 + m * 512;
                    if (rot == 0) {
                        bulk_cp(db, srcB, 512, mb);
                    } else {
                        bulk_cp(db + rot, srcB, 512 - rot, mb);
                        bulk_cp(db, srcB + (512 - rot), rot, mb);
                    }
                }
            }
        }
        return;
    }

    // ---------------- consumers: warp wid owns n-cols [wid*16, wid*16+16) ----------------
    float acc[2][2][4];
#pragma unroll
    for (int i = 0; i < 2; i++)
#pragma unroll
        for (int j = 0; j < 2; j++)
#pragma unroll
            for (int q = 0; q < 4; q++) acc[i][j][q] = 0.0f;

    for (int c = 0; c < NC; c++) {
        const int st = c & 3;
        MBAR_WAIT(sb + OFF_M + st * 8, (c >> 2) & 1);
        const uint32_t Aa = sb + st * STG;
        const uint32_t Ba = sb + st * STG + 4608;
#pragma unroll
        for (int ks = 0; ks < 4; ks++) {
            uint32_t a[2][4], b[2][2];
#pragma unroll
            for (int mt = 0; mt < 2; mt++) {
                const uint32_t base = Aa + (mt * 16 + g) * 144 + (ks * 8 + tig) * 4;
                a[mt][0] = lds32(base);
                a[mt][1] = lds32(base + 8 * 144);
                a[mt][2] = lds32(base + 16);
                a[mt][3] = lds32(base + 8 * 144 + 16);
            }
            const uint32_t k = ks * 8 + tig;
#pragma unroll
            for (int nt = 0; nt < 2; nt++) {
                const uint32_t n = wid * 16 + nt * 8 + g;
                b[nt][0] = lds32(Ba + k * 512 + (((n + 8 * tig) & 127) << 2));
                b[nt][1] = lds32(Ba + (k + 4) * 512 + (((n + 8 * tig) & 127) << 2));
            }
#pragma unroll
            for (int mt = 0; mt < 2; mt++)
#pragma unroll
                for (int nt = 0; nt < 2; nt++) mma8(acc[mt][nt], a[mt], b[nt]);
        }
        __syncwarp();
        if (lid == 0)
            asm volatile("mbarrier.arrive.shared.b64 _, [%0];"
                         :: "r"(sb + OFF_M + 32 + st * 8) : "memory");
    }

    // ---------------- epilogue ----------------
#pragma unroll
    for (int mt = 0; mt < 2; mt++)
#pragma unroll
        for (int half = 0; half < 2; half++) {
            const int m = mt * 16 + g + half * 8;
#pragma unroll
            for (int nt = 0; nt < 2; nt++) {
                const int n = n0 + wid * 16 + nt * 8 + 2 * tig;
                const float v0 = acc[mt][nt][half * 2 + 0];
                const float v1 = acc[mt][nt][half * 2 + 1];
                const float b0 = bias[(size_t)s * NSTR + n];
                const float b1v = bias[(size_t)s * NSTR + n + 1];
                if (G == 1) {
                    float2 o = make_float2(rna(v0 + b0), rna(v1 + b1v));
                    *reinterpret_cast<float2*>(
                        g_H + ((size_t)s * BB + m) * FF + n) = o;
                } else {
                    const size_t xo = ((size_t)m * SQ + s) * EE + n;
                    float2 xr = *reinterpret_cast<const float2*>(resid + xo);
                    float2 o = make_float2(v0 + b0 + xr.x, v1 + b1v + xr.y);
                    *reinterpret_cast<float2*>(outp + xo) = o;
                }
            }
        }
}

__global__ __launch_bounds__(256) void prepass(const float* __restrict__ x) {
    const size_t i = (size_t)blockIdx.x * 256 + threadIdx.x;
    float4 v = reinterpret_cast<const float4*>(x)[i];
    v.x = rna(v.x); v.y = rna(v.y); v.z = rna(v.z); v.w = rna(v.w);
    reinterpret_cast<float4*>(g_Xr)[i] = v;
}

__global__ __launch_bounds__(128) void ln_kernel(
    float* __restrict__ io, const float* __restrict__ gamma,
    const float* __restrict__ beta)
{
    const int row = blockIdx.x, t = threadIdx.x;
    float* p = io + (size_t)row * EE;
    float4 v = reinterpret_cast<float4*>(p)[t];
    float s1 = v.x + v.y + v.z + v.w;
    float s2 = v.x * v.x + v.y * v.y + v.z * v.z + v.w * v.w;
#pragma unroll
    for (int o = 16; o > 0; o >>= 1) {
        s1 += __shfl_xor_sync(0xffffffffu, s1, o);
        s2 += __shfl_xor_sync(0xffffffffu, s2, o);
    }
    __shared__ float sh1[4], sh2[4];
    if ((t & 31) == 0) { sh1[t >> 5] = s1; sh2[t >> 5] = s2; }
    __syncthreads();
    s1 = sh1[0] + sh1[1] + sh1[2] + sh1[3];
    s2 = sh2[0] + sh2[1] + sh2[2] + sh2[3];
    const float mu = s1 * (1.0f / EE);
    const float inv = rsqrtf(s2 * (1.0f / EE) - mu * mu + 1e-5f);
    const float4 ga = reinterpret_cast<const float4*>(gamma)[t];
    const float4 be = reinterpret_cast<const float4*>(beta)[t];
    float4 o;
    o.x = (v.x - mu) * inv * ga.x + be.x;
    o.y = (v.y - mu) * inv * ga.y + be.y;
    o.z = (v.z - mu) * inv * ga.z + be.z;
    o.w = (v.w - mu) * inv * ga.w + be.w;
    reinterpret_cast<float4*>(p)[t] = o;
}

extern "C" void kernel_launch(void* const* d_in, const int* in_sizes, int n_in,
                              void* d_out, int out_size)
{
    const float* x  = (const float*)d_in[0];
    const float* W1 = (const float*)d_in[1];
    const float* b1 = (const float*)d_in[2];
    const float* W2 = (const float*)d_in[3];
    const float* b2 = (const float*)d_in[4];
    const float* ga = (const float*)d_in[5];
    const float* be = (const float*)d_in[6];
    float* out = (float*)d_out;

    cudaFuncSetAttribute(ffn_mma<1>, cudaFuncAttributeMaxDynamicSharedMemorySize, SMB);
    cudaFuncSetAttribute(ffn_mma<2>, cudaFuncAttributeMaxDynamicSharedMemorySize, SMB);

    prepass<<<(BB * SQ * EE / 4) / 256, 256>>>(x);
    ffn_mma<1><<<dim3(FF / 128, SQ), 288, SMB>>>(W1, b1, nullptr, nullptr);
    ffn_mma<2><<<dim3(EE / 128, SQ), 288, SMB>>>(W2, b2, x, out);
    ln_kernel<<<BB * SQ, 128>>>(out, ga, be);
}

// round 6
// speedup vs baseline: 3.1463x; 3.1463x over previous
#include <cuda_runtime.h>
#include <cstdint>

#define BB 32
#define SQ 128
#define EE 512
#define FF 2048

__device__ float g_H[(size_t)SQ * BB * FF];   // [s][b][f]
__device__ float g_Xr[(size_t)BB * SQ * EE];  // tf32-rounded x, [b][s][e]

__device__ __forceinline__ uint32_t smem_u32(const void* p) {
    uint32_t a;
    asm("{ .reg .u64 t; cvta.to.shared.u64 t, %1; cvt.u32.u64 %0, t; }" : "=r"(a) : "l"(p));
    return a;
}
__device__ __forceinline__ float rna(float v) {
    uint32_t r;
    asm("cvt.rna.tf32.f32 %0, %1;" : "=r"(r) : "f"(v));
    return __uint_as_float(r);
}
__device__ __forceinline__ uint32_t lds32(uint32_t a) {
    uint32_t v;
    asm volatile("ld.shared.b32 %0, [%1];" : "=r"(v) : "r"(a));
    return v;
}
__device__ __forceinline__ void sts128(uint32_t a, float4 v) {
    asm volatile("st.shared.v4.b32 [%0], {%1, %2, %3, %4};" :: "r"(a),
        "r"(__float_as_uint(v.x)), "r"(__float_as_uint(v.y)),
        "r"(__float_as_uint(v.z)), "r"(__float_as_uint(v.w)) : "memory");
}
__device__ __forceinline__ void mma8(float* c, const uint32_t* a, const uint32_t* b) {
    asm volatile(
        "mma.sync.aligned.m16n8k8.row.col.f32.tf32.tf32.f32 "
        "{%0,%1,%2,%3}, {%4,%5,%6,%7}, {%8,%9}, {%0,%1,%2,%3};"
        : "+f"(c[0]), "+f"(c[1]), "+f"(c[2]), "+f"(c[3])
        : "r"(a[0]), "r"(a[1]), "r"(a[2]), "r"(a[3]), "r"(b[0]), "r"(b[1]));
}

// Stage: A 32 rows x 144B = 4608B; B 32 k-rows x 544B (512 data + 32 pad) = 17408B.
#define ASTRIDE 144
#define BSTRIDE 544
#define BOFF    4608
#define STG     22016
#define SMB     (2 * STG)

// G==1: H[s][b][f]   = Xr[:,s,:] @ W1[s] + b1[s]   (M=32, N=2048, K=512)
// G==2: out[b][s][e] = H[s] @ W2[s] + b2[s] + x    (M=32, N=512,  K=2048)
template <int G>
__global__ __launch_bounds__(256) void ffn_mma(
    const float* __restrict__ Wt, const float* __restrict__ bias,
    const float* __restrict__ resid, float* __restrict__ outp)
{
    constexpr int K    = (G == 1) ? EE : FF;
    constexpr int NSTR = (G == 1) ? FF : EE;
    constexpr int NC   = K / 32;

    extern __shared__ char smem[];
    const uint32_t sb = smem_u32(smem);
    const int tid = threadIdx.x, wid = tid >> 5, lid = tid & 31;
    const int s = blockIdx.y, n0 = blockIdx.x * 128;
    const uint32_t g = lid >> 2, tig = lid & 3;

    const float* Ab = (G == 1) ? g_Xr + (size_t)s * EE : g_H + (size_t)s * BB * FF;
    const size_t Ar = (G == 1) ? (size_t)SQ * EE : (size_t)FF;
    const float* Wb = Wt + (size_t)s * ((size_t)EE * FF) + n0;

    // load mappings
    const int arow = tid >> 3, ac4 = tid & 7;          // A: 256 x 16B
    const float* agp = Ab + (size_t)arow * Ar + ac4 * 4;
    const uint32_t asp = sb + arow * ASTRIDE + ac4 * 16;

    int brow[4], bc4[4];
#pragma unroll
    for (int i = 0; i < 4; i++) { brow[i] = (tid + i * 256) >> 5; bc4[i] = (tid + i * 256) & 31; }

    float4 pa, pb[4];
    // prefetch chunk 0
    pa = *reinterpret_cast<const float4*>(agp);
#pragma unroll
    for (int i = 0; i < 4; i++)
        pb[i] = *reinterpret_cast<const float4*>(Wb + (size_t)brow[i] * NSTR + bc4[i] * 4);
    // store chunk 0
    sts128(asp, pa);
#pragma unroll
    for (int i = 0; i < 4; i++)
        sts128(sb + BOFF + brow[i] * BSTRIDE + bc4[i] * 16, pb[i]);

    float acc[2][2][4];
#pragma unroll
    for (int i = 0; i < 2; i++)
#pragma unroll
        for (int j = 0; j < 2; j++)
#pragma unroll
            for (int q = 0; q < 4; q++) acc[i][j][q] = 0.0f;

    for (int c = 0; c < NC; c++) {
        __syncthreads();
        const int k1 = (c + 1) * 32;
        if (c + 1 < NC) {
            pa = *reinterpret_cast<const float4*>(agp + k1);
#pragma unroll
            for (int i = 0; i < 4; i++)
                pb[i] = *reinterpret_cast<const float4*>(
                    Wb + (size_t)(k1 + brow[i]) * NSTR + bc4[i] * 4);
        }
        const uint32_t Aa = sb + (c & 1) * STG;
        const uint32_t Ba = Aa + BOFF;
#pragma unroll
        for (int ks = 0; ks < 4; ks++) {
            uint32_t a[2][4], b[2][2];
#pragma unroll
            for (int mt = 0; mt < 2; mt++) {
                const uint32_t base = Aa + (mt * 16 + g) * ASTRIDE + (ks * 8 + tig) * 4;
                a[mt][0] = lds32(base);
                a[mt][1] = lds32(base + 8 * ASTRIDE);
                a[mt][2] = lds32(base + 16);
                a[mt][3] = lds32(base + 8 * ASTRIDE + 16);
            }
            const uint32_t kk = ks * 8 + tig;
#pragma unroll
            for (int nt = 0; nt < 2; nt++) {
                const uint32_t n = wid * 16 + nt * 8 + g;
                b[nt][0] = lds32(Ba + kk * BSTRIDE + n * 4);
                b[nt][1] = lds32(Ba + (kk + 4) * BSTRIDE + n * 4);
            }
#pragma unroll
            for (int mt = 0; mt < 2; mt++)
#pragma unroll
                for (int nt = 0; nt < 2; nt++) mma8(acc[mt][nt], a[mt], b[nt]);
        }
        if (c + 1 < NC) {
            const uint32_t nbuf = sb + ((c + 1) & 1) * STG;
            sts128(nbuf + arow * ASTRIDE + ac4 * 16, pa);
#pragma unroll
            for (int i = 0; i < 4; i++)
                sts128(nbuf + BOFF + brow[i] * BSTRIDE + bc4[i] * 16, pb[i]);
        }
    }

    // epilogue (mapping verified in R5)
#pragma unroll
    for (int mt = 0; mt < 2; mt++)
#pragma unroll
        for (int half = 0; half < 2; half++) {
            const int m = mt * 16 + g + half * 8;
#pragma unroll
            for (int nt = 0; nt < 2; nt++) {
                const int n = n0 + wid * 16 + nt * 8 + 2 * tig;
                const float v0 = acc[mt][nt][half * 2 + 0];
                const float v1 = acc[mt][nt][half * 2 + 1];
                const float b0 = bias[(size_t)s * NSTR + n];
                const float b1v = bias[(size_t)s * NSTR + n + 1];
                if (G == 1) {
                    float2 o = make_float2(rna(v0 + b0), rna(v1 + b1v));
                    *reinterpret_cast<float2*>(g_H + ((size_t)s * BB + m) * FF + n) = o;
                } else {
                    const size_t xo = ((size_t)m * SQ + s) * EE + n;
                    float2 xr = *reinterpret_cast<const float2*>(resid + xo);
                    float2 o = make_float2(v0 + b0 + xr.x, v1 + b1v + xr.y);
                    *reinterpret_cast<float2*>(outp + xo) = o;
                }
            }
        }
}

__global__ __launch_bounds__(256) void prepass(const float* __restrict__ x) {
    const size_t i = (size_t)blockIdx.x * 256 + threadIdx.x;
    float4 v = reinterpret_cast<const float4*>(x)[i];
    v.x = rna(v.x); v.y = rna(v.y); v.z = rna(v.z); v.w = rna(v.w);
    reinterpret_cast<float4*>(g_Xr)[i] = v;
}

__global__ __launch_bounds__(128) void ln_kernel(
    float* __restrict__ io, const float* __restrict__ gamma,
    const float* __restrict__ beta)
{
    const int row = blockIdx.x, t = threadIdx.x;
    float* p = io + (size_t)row * EE;
    float4 v = reinterpret_cast<float4*>(p)[t];
    float s1 = v.x + v.y + v.z + v.w;
    float s2 = v.x * v.x + v.y * v.y + v.z * v.z + v.w * v.w;
#pragma unroll
    for (int o = 16; o > 0; o >>= 1) {
        s1 += __shfl_xor_sync(0xffffffffu, s1, o);
        s2 += __shfl_xor_sync(0xffffffffu, s2, o);
    }
    __shared__ float sh1[4], sh2[4];
    if ((t & 31) == 0) { sh1[t >> 5] = s1; sh2[t >> 5] = s2; }
    __syncthreads();
    s1 = sh1[0] + sh1[1] + sh1[2] + sh1[3];
    s2 = sh2[0] + sh2[1] + sh2[2] + sh2[3];
    const float mu = s1 * (1.0f / EE);
    const float inv = rsqrtf(s2 * (1.0f / EE) - mu * mu + 1e-5f);
    const float4 ga = reinterpret_cast<const float4*>(gamma)[t];
    const float4 be = reinterpret_cast<const float4*>(beta)[t];
    float4 o;
    o.x = (v.x - mu) * inv * ga.x + be.x;
    o.y = (v.y - mu) * inv * ga.y + be.y;
    o.z = (v.z - mu) * inv * ga.z + be.z;
    o.w = (v.w - mu) * inv * ga.w + be.w;
    reinterpret_cast<float4*>(p)[t] = o;
}

extern "C" void kernel_launch(void* const* d_in, const int* in_sizes, int n_in,
                              void* d_out, int out_size)
{
    const float* x  = (const float*)d_in[0];
    const float* W1 = (const float*)d_in[1];
    const float* b1 = (const float*)d_in[2];
    const float* W2 = (const float*)d_in[3];
    const float* b2 = (const float*)d_in[4];
    const float* ga = (const float*)d_in[5];
    const float* be = (const float*)d_in[6];
    float* out = (float*)d_out;

    prepass<<<(BB * SQ * EE / 4) / 256, 256>>>(x);
    ffn_mma<1><<<dim3(FF / 128, SQ), 256, SMB>>>(W1, b1, nullptr, nullptr);
    ffn_mma<2><<<dim3(EE / 128, SQ), 256, SMB>>>(W2, b2, x, out);
    ln_kernel<<<BB * SQ, 128>>>(out, ga, be);
}

// round 7
// speedup vs baseline: 3.3496x; 1.0646x over previous
#include <cuda_runtime.h>
#include <cstdint>

#define BB 32
#define SQ 128
#define EE 512
#define FF 2048

__device__ float g_H[(size_t)SQ * BB * FF];   // [s][b][f]

__device__ __forceinline__ uint32_t smem_u32(const void* p) {
    uint32_t a;
    asm("{ .reg .u64 t; cvta.to.shared.u64 t, %1; cvt.u32.u64 %0, t; }" : "=r"(a) : "l"(p));
    return a;
}
__device__ __forceinline__ float rna(float v) {
    uint32_t r;
    asm("cvt.rna.tf32.f32 %0, %1;" : "=r"(r) : "f"(v));
    return __uint_as_float(r);
}
__device__ __forceinline__ uint32_t lds32(uint32_t a) {
    uint32_t v;
    asm volatile("ld.shared.b32 %0, [%1];" : "=r"(v) : "r"(a));
    return v;
}
__device__ __forceinline__ void sts128(uint32_t a, float4 v) {
    asm volatile("st.shared.v4.b32 [%0], {%1, %2, %3, %4};" :: "r"(a),
        "r"(__float_as_uint(v.x)), "r"(__float_as_uint(v.y)),
        "r"(__float_as_uint(v.z)), "r"(__float_as_uint(v.w)) : "memory");
}
__device__ __forceinline__ void mma8(float* c, const uint32_t* a, const uint32_t* b) {
    asm volatile(
        "mma.sync.aligned.m16n8k8.row.col.f32.tf32.tf32.f32 "
        "{%0,%1,%2,%3}, {%4,%5,%6,%7}, {%8,%9}, {%0,%1,%2,%3};"
        : "+f"(c[0]), "+f"(c[1]), "+f"(c[2]), "+f"(c[3])
        : "r"(a[0]), "r"(a[1]), "r"(a[2]), "r"(a[3]), "r"(b[0]), "r"(b[1]));
}

// Stage: A 32 rows x 144B = 4608B; B 32 k-rows x 1056B (1024 data + 32 pad) = 33792B.
#define ASTRIDE 144
#define BSTRIDE 1056
#define BOFF    4608
#define STG     38400
#define SMB     (2 * STG)

// BN=256: 8 warps x 32 n-cols (4 x n8 tiles). BK=32, 2-stage reg-prefetch.
// G==1: H[s][b][f]   = rna(x[:,s,:]) @ W1[s] + b1[s]   (M=32, N=2048, K=512)
// G==2: out[b][s][e] = H[s] @ W2[s] + b2[s] + x        (M=32, N=512,  K=2048)
template <int G>
__global__ __launch_bounds__(256) void ffn_mma(
    const float* __restrict__ Wt, const float* __restrict__ bias,
    const float* __restrict__ Ain, const float* __restrict__ resid,
    float* __restrict__ outp)
{
    constexpr int K    = (G == 1) ? EE : FF;
    constexpr int NSTR = (G == 1) ? FF : EE;
    constexpr int NC   = K / 32;

    extern __shared__ char smem[];
    const uint32_t sb = smem_u32(smem);
    const int tid = threadIdx.x, wid = tid >> 5, lid = tid & 31;
    const int s = blockIdx.y, n0 = blockIdx.x * 256;
    const uint32_t g = lid >> 2, tig = lid & 3;

    const float* Ab = (G == 1) ? Ain + (size_t)s * EE : g_H + (size_t)s * BB * FF;
    const size_t Ar = (G == 1) ? (size_t)SQ * EE : (size_t)FF;
    const float* Wb = Wt + (size_t)s * ((size_t)EE * FF) + n0;

    // A: 256 threads x 1 float4 (32 rows x 8 f4)
    const int arow = tid >> 3, ac4 = tid & 7;
    const float* agp = Ab + (size_t)arow * Ar + ac4 * 4;
    const uint32_t asp = sb + arow * ASTRIDE + ac4 * 16;
    // B: 32 rows x 64 f4 = 2048 f4 -> 8 per thread
    int brow[8], bc4[8];
#pragma unroll
    for (int i = 0; i < 8; i++) {
        const int idx = tid + i * 256;
        brow[i] = idx >> 6;
        bc4[i]  = idx & 63;
    }

    float4 pa, pb[8];
    pa = *reinterpret_cast<const float4*>(agp);
#pragma unroll
    for (int i = 0; i < 8; i++)
        pb[i] = *reinterpret_cast<const float4*>(Wb + (size_t)brow[i] * NSTR + bc4[i] * 4);
    if (G == 1) { pa.x = rna(pa.x); pa.y = rna(pa.y); pa.z = rna(pa.z); pa.w = rna(pa.w); }
    sts128(asp, pa);
#pragma unroll
    for (int i = 0; i < 8; i++)
        sts128(sb + BOFF + brow[i] * BSTRIDE + bc4[i] * 16, pb[i]);

    float acc[2][4][4];
#pragma unroll
    for (int i = 0; i < 2; i++)
#pragma unroll
        for (int j = 0; j < 4; j++)
#pragma unroll
            for (int q = 0; q < 4; q++) acc[i][j][q] = 0.0f;

    for (int c = 0; c < NC; c++) {
        __syncthreads();
        const int k1 = (c + 1) * 32;
        if (c + 1 < NC) {
            pa = *reinterpret_cast<const float4*>(agp + k1);
#pragma unroll
            for (int i = 0; i < 8; i++)
                pb[i] = *reinterpret_cast<const float4*>(
                    Wb + (size_t)(k1 + brow[i]) * NSTR + bc4[i] * 4);
            if (G == 1) { pa.x = rna(pa.x); pa.y = rna(pa.y); pa.z = rna(pa.z); pa.w = rna(pa.w); }
        }
        const uint32_t Aa = sb + (c & 1) * STG;
        const uint32_t Ba = Aa + BOFF;
#pragma unroll
        for (int ks = 0; ks < 4; ks++) {
            uint32_t a[2][4], b[4][2];
#pragma unroll
            for (int mt = 0; mt < 2; mt++) {
                const uint32_t base = Aa + (mt * 16 + g) * ASTRIDE + (ks * 8 + tig) * 4;
                a[mt][0] = lds32(base);
                a[mt][1] = lds32(base + 8 * ASTRIDE);
                a[mt][2] = lds32(base + 16);
                a[mt][3] = lds32(base + 8 * ASTRIDE + 16);
            }
            const uint32_t kk = ks * 8 + tig;
#pragma unroll
            for (int nt = 0; nt < 4; nt++) {
                const uint32_t n = wid * 32 + nt * 8 + g;
                b[nt][0] = lds32(Ba + kk * BSTRIDE + n * 4);
                b[nt][1] = lds32(Ba + (kk + 4) * BSTRIDE + n * 4);
            }
#pragma unroll
            for (int mt = 0; mt < 2; mt++)
#pragma unroll
                for (int nt = 0; nt < 4; nt++) mma8(acc[mt][nt], a[mt], b[nt]);
        }
        if (c + 1 < NC) {
            const uint32_t nbuf = sb + ((c + 1) & 1) * STG;
            sts128(nbuf + arow * ASTRIDE + ac4 * 16, pa);
#pragma unroll
            for (int i = 0; i < 8; i++)
                sts128(nbuf + BOFF + brow[i] * BSTRIDE + bc4[i] * 16, pb[i]);
        }
    }

    // epilogue (fragment mapping verified in R5/R6)
#pragma unroll
    for (int mt = 0; mt < 2; mt++)
#pragma unroll
        for (int half = 0; half < 2; half++) {
            const int m = mt * 16 + g + half * 8;
#pragma unroll
            for (int nt = 0; nt < 4; nt++) {
                const int n = n0 + wid * 32 + nt * 8 + 2 * tig;
                const float v0 = acc[mt][nt][half * 2 + 0];
                const float v1 = acc[mt][nt][half * 2 + 1];
                const float b0 = bias[(size_t)s * NSTR + n];
                const float b1v = bias[(size_t)s * NSTR + n + 1];
                if (G == 1) {
                    float2 o = make_float2(rna(v0 + b0), rna(v1 + b1v));
                    *reinterpret_cast<float2*>(g_H + ((size_t)s * BB + m) * FF + n) = o;
                } else {
                    const size_t xo = ((size_t)m * SQ + s) * EE + n;
                    float2 xr = *reinterpret_cast<const float2*>(resid + xo);
                    float2 o = make_float2(v0 + b0 + xr.x, v1 + b1v + xr.y);
                    *reinterpret_cast<float2*>(outp + xo) = o;
                }
            }
        }
}

__global__ __launch_bounds__(128) void ln_kernel(
    float* __restrict__ io, const float* __restrict__ gamma,
    const float* __restrict__ beta)
{
    const int row = blockIdx.x, t = threadIdx.x;
    float* p = io + (size_t)row * EE;
    float4 v = reinterpret_cast<float4*>(p)[t];
    float s1 = v.x + v.y + v.z + v.w;
    float s2 = v.x * v.x + v.y * v.y + v.z * v.z + v.w * v.w;
#pragma unroll
    for (int o = 16; o > 0; o >>= 1) {
        s1 += __shfl_xor_sync(0xffffffffu, s1, o);
        s2 += __shfl_xor_sync(0xffffffffu, s2, o);
    }
    __shared__ float sh1[4], sh2[4];
    if ((t & 31) == 0) { sh1[t >> 5] = s1; sh2[t >> 5] = s2; }
    __syncthreads();
    s1 = sh1[0] + sh1[1] + sh1[2] + sh1[3];
    s2 = sh2[0] + sh2[1] + sh2[2] + sh2[3];
    const float mu = s1 * (1.0f / EE);
    const float inv = rsqrtf(s2 * (1.0f / EE) - mu * mu + 1e-5f);
    const float4 ga = reinterpret_cast<const float4*>(gamma)[t];
    const float4 be = reinterpret_cast<const float4*>(beta)[t];
    float4 o;
    o.x = (v.x - mu) * inv * ga.x + be.x;
    o.y = (v.y - mu) * inv * ga.y + be.y;
    o.z = (v.z - mu) * inv * ga.z + be.z;
    o.w = (v.w - mu) * inv * ga.w + be.w;
    reinterpret_cast<float4*>(p)[t] = o;
}

extern "C" void kernel_launch(void* const* d_in, const int* in_sizes, int n_in,
                              void* d_out, int out_size)
{
    const float* x  = (const float*)d_in[0];
    const float* W1 = (const float*)d_in[1];
    const float* b1 = (const float*)d_in[2];
    const float* W2 = (const float*)d_in[3];
    const float* b2 = (const float*)d_in[4];
    const float* ga = (const float*)d_in[5];
    const float* be = (const float*)d_in[6];
    float* out = (float*)d_out;

    static int init = 0;
    if (!init) {
        cudaFuncSetAttribute(ffn_mma<1>, cudaFuncAttributeMaxDynamicSharedMemorySize, SMB);
        cudaFuncSetAttribute(ffn_mma<2>, cudaFuncAttributeMaxDynamicSharedMemorySize, SMB);
        init = 1;
    }

    ffn_mma<1><<<dim3(FF / 256, SQ), 256, SMB>>>(W1, b1, x, nullptr, nullptr);
    ffn_mma<2><<<dim3(EE / 256, SQ), 256, SMB>>>(W2, b2, nullptr, x, out);
    ln_kernel<<<BB * SQ, 128>>>(out, ga, be);
}

// round 8
// speedup vs baseline: 3.7559x; 1.1213x over previous
#include <cuda_runtime.h>
#include <cstdint>

#define BB 32
#define SQ 128
#define EE 512
#define FF 2048

__device__ float g_H[(size_t)SQ * BB * FF];   // [s][b][f]

__device__ __forceinline__ uint32_t smem_u32(const void* p) {
    uint32_t a;
    asm("{ .reg .u64 t; cvta.to.shared.u64 t, %1; cvt.u32.u64 %0, t; }" : "=r"(a) : "l"(p));
    return a;
}
__device__ __forceinline__ float rna(float v) {
    uint32_t r;
    asm("cvt.rna.tf32.f32 %0, %1;" : "=r"(r) : "f"(v));
    return __uint_as_float(r);
}
__device__ __forceinline__ uint32_t lds32(uint32_t a) {
    uint32_t v;
    asm volatile("ld.shared.b32 %0, [%1];" : "=r"(v) : "r"(a));
    return v;
}
__device__ __forceinline__ void sts128(uint32_t a, float4 v) {
    asm volatile("st.shared.v4.b32 [%0], {%1, %2, %3, %4};" :: "r"(a),
        "r"(__float_as_uint(v.x)), "r"(__float_as_uint(v.y)),
        "r"(__float_as_uint(v.z)), "r"(__float_as_uint(v.w)) : "memory");
}
__device__ __forceinline__ void cpa16(uint32_t dst, const void* src) {
    asm volatile("cp.async.cg.shared.global [%0], [%1], 16;" :: "r"(dst), "l"(src) : "memory");
}
__device__ __forceinline__ void cpa_commit() {
    asm volatile("cp.async.commit_group;" ::: "memory");
}
__device__ __forceinline__ void cpa_wait0() {
    asm volatile("cp.async.wait_group 0;" ::: "memory");
}
__device__ __forceinline__ void mma8(float* c, const uint32_t* a, const uint32_t* b) {
    asm volatile(
        "mma.sync.aligned.m16n8k8.row.col.f32.tf32.tf32.f32 "
        "{%0,%1,%2,%3}, {%4,%5,%6,%7}, {%8,%9}, {%0,%1,%2,%3};"
        : "+f"(c[0]), "+f"(c[1]), "+f"(c[2]), "+f"(c[3])
        : "r"(a[0]), "r"(a[1]), "r"(a[2]), "r"(a[3]), "r"(b[0]), "r"(b[1]));
}

// Stage: A 32 x 144B = 4608B; B 32 k-rows x 1056B (1024 + 32 pad) = 33792B.
#define ASTRIDE 144
#define BSTRIDE 1056
#define BOFF    4608
#define STG     38400
#define SMB     (2 * STG)

// BN=256, BK=32. A: LDG->STS (1 f4/thr, 1 chunk ahead). B: cp.async double-buffer.
// G==1: H[s][b][f]   = rna(x[:,s,:]) @ W1[s] + b1[s]   (M=32, N=2048, K=512)
// G==2: out[b][s][e] = H[s] @ W2[s] + b2[s] + x        (M=32, N=512,  K=2048)
template <int G>
__global__ __launch_bounds__(256, 3) void ffn_mma(
    const float* __restrict__ Wt, const float* __restrict__ bias,
    const float* __restrict__ Ain, const float* __restrict__ resid,
    float* __restrict__ outp)
{
    constexpr int K    = (G == 1) ? EE : FF;
    constexpr int NSTR = (G == 1) ? FF : EE;
    constexpr int NC   = K / 32;

    extern __shared__ char smem[];
    const uint32_t sb = smem_u32(smem);
    const int tid = threadIdx.x, wid = tid >> 5, lid = tid & 31;
    const int s = blockIdx.y, n0 = blockIdx.x * 256;
    const uint32_t g = lid >> 2, tig = lid & 3;

    const float* Ab = (G == 1) ? Ain + (size_t)s * EE : g_H + (size_t)s * BB * FF;
    const size_t Ar = (G == 1) ? (size_t)SQ * EE : (size_t)FF;
    const float* Wb = Wt + (size_t)s * ((size_t)EE * FF) + n0;

    // A: 256 threads x 1 float4 (32 rows x 8 f4)
    const int arow = tid >> 3, ac4 = tid & 7;
    const float* agp = Ab + (size_t)arow * Ar + ac4 * 4;
    const uint32_t aso = arow * ASTRIDE + ac4 * 16;
    // B: 32 rows x 64 f4 -> 8 f4 per thread; thread covers rows tid>>6 + {0,4,..28}? No:
    // idx = tid + i*256 -> row idx>>6 (0..31), col idx&63.
    const int brow0 = tid >> 6, bc4 = tid & 63;

    float4 pa;
    // prologue: B0 via cp.async, A0 via ldg+sts
    {
        const uint32_t bs0 = sb + BOFF;
#pragma unroll
        for (int i = 0; i < 8; i++) {
            const int r = brow0 + i * 4;
            cpa16(bs0 + r * BSTRIDE + bc4 * 16, Wb + (size_t)r * NSTR + bc4 * 4);
        }
        cpa_commit();
        pa = *reinterpret_cast<const float4*>(agp);
        if (G == 1) { pa.x = rna(pa.x); pa.y = rna(pa.y); pa.z = rna(pa.z); pa.w = rna(pa.w); }
        sts128(sb + aso, pa);
    }

    float acc[2][4][4];
#pragma unroll
    for (int i = 0; i < 2; i++)
#pragma unroll
        for (int j = 0; j < 4; j++)
#pragma unroll
            for (int q = 0; q < 4; q++) acc[i][j][q] = 0.0f;

    for (int c = 0; c < NC; c++) {
        const int k1 = (c + 1) * 32;
        if (c + 1 < NC) {
            pa = *reinterpret_cast<const float4*>(agp + k1);
            if (G == 1) { pa.x = rna(pa.x); pa.y = rna(pa.y); pa.z = rna(pa.z); pa.w = rna(pa.w); }
        }
        cpa_wait0();          // B_c landed
        __syncthreads();      // everyone done with (c-1) buffers
        if (c + 1 < NC) {
            const uint32_t nb = sb + ((c + 1) & 1) * STG;
#pragma unroll
            for (int i = 0; i < 8; i++) {
                const int r = brow0 + i * 4;
                cpa16(nb + BOFF + r * BSTRIDE + bc4 * 16,
                      Wb + (size_t)(k1 + r) * NSTR + bc4 * 4);
            }
            cpa_commit();
            sts128(nb + aso, pa);
        }
        const uint32_t Aa = sb + (c & 1) * STG;
        const uint32_t Ba = Aa + BOFF;
#pragma unroll
        for (int ks = 0; ks < 4; ks++) {
            uint32_t a[2][4], b[4][2];
#pragma unroll
            for (int mt = 0; mt < 2; mt++) {
                const uint32_t base = Aa + (mt * 16 + g) * ASTRIDE + (ks * 8 + tig) * 4;
                a[mt][0] = lds32(base);
                a[mt][1] = lds32(base + 8 * ASTRIDE);
                a[mt][2] = lds32(base + 16);
                a[mt][3] = lds32(base + 8 * ASTRIDE + 16);
            }
            const uint32_t kk = ks * 8 + tig;
#pragma unroll
            for (int nt = 0; nt < 4; nt++) {
                const uint32_t n = wid * 32 + nt * 8 + g;
                b[nt][0] = lds32(Ba + kk * BSTRIDE + n * 4);
                b[nt][1] = lds32(Ba + (kk + 4) * BSTRIDE + n * 4);
            }
#pragma unroll
            for (int mt = 0; mt < 2; mt++)
#pragma unroll
                for (int nt = 0; nt < 4; nt++) mma8(acc[mt][nt], a[mt], b[nt]);
        }
    }

    // epilogue (fragment mapping verified R5-R7)
#pragma unroll
    for (int mt = 0; mt < 2; mt++)
#pragma unroll
        for (int half = 0; half < 2; half++) {
            const int m = mt * 16 + g + half * 8;
#pragma unroll
            for (int nt = 0; nt < 4; nt++) {
                const int n = n0 + wid * 32 + nt * 8 + 2 * tig;
                const float v0 = acc[mt][nt][half * 2 + 0];
                const float v1 = acc[mt][nt][half * 2 + 1];
                const float b0 = bias[(size_t)s * NSTR + n];
                const float b1v = bias[(size_t)s * NSTR + n + 1];
                if (G == 1) {
                    float2 o = make_float2(rna(v0 + b0), rna(v1 + b1v));
                    *reinterpret_cast<float2*>(g_H + ((size_t)s * BB + m) * FF + n) = o;
                } else {
                    const size_t xo = ((size_t)m * SQ + s) * EE + n;
                    float2 xr = *reinterpret_cast<const float2*>(resid + xo);
                    float2 o = make_float2(v0 + b0 + xr.x, v1 + b1v + xr.y);
                    *reinterpret_cast<float2*>(outp + xo) = o;
                }
            }
        }
}

__global__ __launch_bounds__(128) void ln_kernel(
    float* __restrict__ io, const float* __restrict__ gamma,
    const float* __restrict__ beta)
{
    const int row = blockIdx.x, t = threadIdx.x;
    float* p = io + (size_t)row * EE;
    float4 v = reinterpret_cast<float4*>(p)[t];
    float s1 = v.x + v.y + v.z + v.w;
    float s2 = v.x * v.x + v.y * v.y + v.z * v.z + v.w * v.w;
#pragma unroll
    for (int o = 16; o > 0; o >>= 1) {
        s1 += __shfl_xor_sync(0xffffffffu, s1, o);
        s2 += __shfl_xor_sync(0xffffffffu, s2, o);
    }
    __shared__ float sh1[4], sh2[4];
    if ((t & 31) == 0) { sh1[t >> 5] = s1; sh2[t >> 5] = s2; }
    __syncthreads();
    s1 = sh1[0] + sh1[1] + sh1[2] + sh1[3];
    s2 = sh2[0] + sh2[1] + sh2[2] + sh2[3];
    const float mu = s1 * (1.0f / EE);
    const float inv = rsqrtf(s2 * (1.0f / EE) - mu * mu + 1e-5f);
    const float4 ga = reinterpret_cast<const float4*>(gamma)[t];
    const float4 be = reinterpret_cast<const float4*>(beta)[t];
    float4 o;
    o.x = (v.x - mu) * inv * ga.x + be.x;
    o.y = (v.y - mu) * inv * ga.y + be.y;
    o.z = (v.z - mu) * inv * ga.z + be.z;
    o.w = (v.w - mu) * inv * ga.w + be.w;
    reinterpret_cast<float4*>(p)[t] = o;
}

extern "C" void kernel_launch(void* const* d_in, const int* in_sizes, int n_in,
                              void* d_out, int out_size)
{
    const float* x  = (const float*)d_in[0];
    const float* W1 = (const float*)d_in[1];
    const float* b1 = (const float*)d_in[2];
    const float* W2 = (const float*)d_in[3];
    const float* b2 = (const float*)d_in[4];
    const float* ga = (const float*)d_in[5];
    const float* be = (const float*)d_in[6];
    float* out = (float*)d_out;

    static int init = 0;
    if (!init) {
        cudaFuncSetAttribute(ffn_mma<1>, cudaFuncAttributeMaxDynamicSharedMemorySize, SMB);
        cudaFuncSetAttribute(ffn_mma<2>, cudaFuncAttributeMaxDynamicSharedMemorySize, SMB);
        cudaFuncSetAttribute(ffn_mma<1>, cudaFuncAttributePreferredSharedMemoryCarveout, 100);
        cudaFuncSetAttribute(ffn_mma<2>, cudaFuncAttributePreferredSharedMemoryCarveout, 100);
        init = 1;
    }

    ffn_mma<1><<<dim3(FF / 256, SQ), 256, SMB>>>(W1, b1, x, nullptr, nullptr);
    ffn_mma<2><<<dim3(EE / 256, SQ), 256, SMB>>>(W2, b2, nullptr, x, out);
    ln_kernel<<<BB * SQ, 128>>>(out, ga, be);
}

// round 9
// speedup vs baseline: 3.8761x; 1.0320x over previous
#include <cuda_runtime.h>
#include <cstdint>

#define BB 32
#define SQ 128
#define EE 512
#define FF 2048

__device__ float g_H[(size_t)SQ * BB * FF];    // [s][b][f]
__device__ float g_Xr[(size_t)BB * SQ * EE];   // tf32-rounded x

#define STGSZ 18944   // A: 32x80 = 2560; B: 16x1024 = 16384
#define SMB   (4 * STGSZ)

__device__ __forceinline__ uint32_t smem_u32(const void* p) {
    uint32_t a;
    asm("{ .reg .u64 t; cvta.to.shared.u64 t, %1; cvt.u32.u64 %0, t; }" : "=r"(a) : "l"(p));
    return a;
}
__device__ __forceinline__ float rna(float v) {
    uint32_t r;
    asm("cvt.rna.tf32.f32 %0, %1;" : "=r"(r) : "f"(v));
    return __uint_as_float(r);
}
__device__ __forceinline__ uint32_t lds32(uint32_t a) {
    uint32_t v;
    asm volatile("ld.shared.b32 %0, [%1];" : "=r"(v) : "r"(a));
    return v;
}
__device__ __forceinline__ void cpa16(uint32_t dst, const void* src) {
    asm volatile("cp.async.cg.shared.global [%0], [%1], 16;" :: "r"(dst), "l"(src) : "memory");
}
__device__ __forceinline__ void cpa_commit() {
    asm volatile("cp.async.commit_group;" ::: "memory");
}
__device__ __forceinline__ void cpa_wait2() {
    asm volatile("cp.async.wait_group 2;" ::: "memory");
}
__device__ __forceinline__ void mma8(float* c, const uint32_t* a, const uint32_t* b) {
    asm volatile(
        "mma.sync.aligned.m16n8k8.row.col.f32.tf32.tf32.f32 "
        "{%0,%1,%2,%3}, {%4,%5,%6,%7}, {%8,%9}, {%0,%1,%2,%3};"
        : "+f"(c[0]), "+f"(c[1]), "+f"(c[2]), "+f"(c[3])
        : "r"(a[0]), "r"(a[1]), "r"(a[2]), "r"(a[3]), "r"(b[0]), "r"(b[1]));
}

// BN=256, BK=16, 4-stage cp.async ring (3 chunks in flight), wait_group 2.
// G==1: H[s][b][f]   = Xr[:,s,:] @ W1[s] + b1[s]   (M=32, N=2048, K=512)
// G==2: out[b][s][e] = H[s] @ W2[s] + b2[s] + x    (M=32, N=512,  K=2048)
template <int G>
__global__ __launch_bounds__(256, 3) void ffn_mma(
    const float* __restrict__ Wt, const float* __restrict__ bias,
    const float* __restrict__ resid, float* __restrict__ outp)
{
    constexpr int K    = (G == 1) ? EE : FF;
    constexpr int NSTR = (G == 1) ? FF : EE;
    constexpr int NCH  = K / 16;

    extern __shared__ char smem[];
    const uint32_t sb = smem_u32(smem);
    const int tid = threadIdx.x, wid = tid >> 5, lid = tid & 31;
    const int s = blockIdx.y, n0 = blockIdx.x * 256;
    const uint32_t g = lid >> 2, tig = lid & 3;

    const float* Ab = (G == 1) ? g_Xr + (size_t)s * EE : g_H + (size_t)s * BB * FF;
    const size_t Ar = (G == 1) ? (size_t)SQ * EE : (size_t)FF;
    const float* Wb = Wt + (size_t)s * ((size_t)EE * FF) + n0;

    const int arow = tid >> 2, ac4 = tid & 3;          // A: threads < 128
    const int br0 = tid >> 6, bc4 = tid & 63;          // B: 4 f4 per thread

    auto issue = [&](int c) {
        const uint32_t stg = sb + (c & 3) * STGSZ;
        const int k0 = c * 16;
        if (tid < 128)
            cpa16(stg + arow * 80 + ac4 * 16, Ab + (size_t)arow * Ar + k0 + ac4 * 4);
#pragma unroll
        for (int i = 0; i < 4; i++) {
            const int r = br0 + i * 4;
            cpa16(stg + 2560 + r * 1024 + (((bc4 + 2 * (r & 3)) & 63) << 4),
                  Wb + (size_t)(k0 + r) * NSTR + bc4 * 4);
        }
        cpa_commit();
    };

    issue(0); issue(1); issue(2);

    float acc[2][4][4];
#pragma unroll
    for (int i = 0; i < 2; i++)
#pragma unroll
        for (int j = 0; j < 4; j++)
#pragma unroll
            for (int q = 0; q < 4; q++) acc[i][j][q] = 0.0f;

    // per-thread b addressing constants
    uint32_t bcol[4];
#pragma unroll
    for (int nt = 0; nt < 4; nt++) {
        const uint32_t n = wid * 32 + nt * 8 + g;
        bcol[nt] = ((((n >> 2) + 2 * tig) & 63) << 4) + (n & 3) * 4;
    }

#pragma unroll 1
    for (int c = 0; c < NCH; c++) {
        cpa_wait2();
        __syncthreads();
        if (c + 3 < NCH) issue(c + 3); else cpa_commit();
        const uint32_t Aa = sb + (c & 3) * STGSZ;
        const uint32_t Ba = Aa + 2560;
#pragma unroll
        for (int ks = 0; ks < 2; ks++) {
            uint32_t a[2][4], b[4][2];
#pragma unroll
            for (int mt = 0; mt < 2; mt++) {
                const uint32_t base = Aa + (mt * 16 + g) * 80 + (ks * 8 + tig) * 4;
                a[mt][0] = lds32(base);
                a[mt][1] = lds32(base + 8 * 80);
                a[mt][2] = lds32(base + 16);
                a[mt][3] = lds32(base + 8 * 80 + 16);
            }
            const uint32_t kk = ks * 8 + tig;
#pragma unroll
            for (int nt = 0; nt < 4; nt++) {
                b[nt][0] = lds32(Ba + kk * 1024 + bcol[nt]);
                b[nt][1] = lds32(Ba + (kk + 4) * 1024 + bcol[nt]);
            }
#pragma unroll
            for (int mt = 0; mt < 2; mt++)
#pragma unroll
                for (int nt = 0; nt < 4; nt++) mma8(acc[mt][nt], a[mt], b[nt]);
        }
    }

    // epilogue (fragment mapping verified R5-R8)
#pragma unroll
    for (int mt = 0; mt < 2; mt++)
#pragma unroll
        for (int half = 0; half < 2; half++) {
            const int m = mt * 16 + g + half * 8;
#pragma unroll
            for (int nt = 0; nt < 4; nt++) {
                const int n = n0 + wid * 32 + nt * 8 + 2 * tig;
                const float v0 = acc[mt][nt][half * 2 + 0];
                const float v1 = acc[mt][nt][half * 2 + 1];
                const float b0 = bias[(size_t)s * NSTR + n];
                const float b1v = bias[(size_t)s * NSTR + n + 1];
                if (G == 1) {
                    float2 o = make_float2(rna(v0 + b0), rna(v1 + b1v));
                    *reinterpret_cast<float2*>(g_H + ((size_t)s * BB + m) * FF + n) = o;
                } else {
                    const size_t xo = ((size_t)m * SQ + s) * EE + n;
                    float2 xr = *reinterpret_cast<const float2*>(resid + xo);
                    float2 o = make_float2(v0 + b0 + xr.x, v1 + b1v + xr.y);
                    *reinterpret_cast<float2*>(outp + xo) = o;
                }
            }
        }
}

__global__ __launch_bounds__(256) void prepass(const float* __restrict__ x) {
    const size_t i = (size_t)blockIdx.x * 256 + threadIdx.x;
    float4 v = reinterpret_cast<const float4*>(x)[i];
    v.x = rna(v.x); v.y = rna(v.y); v.z = rna(v.z); v.w = rna(v.w);
    reinterpret_cast<float4*>(g_Xr)[i] = v;
}

__global__ __launch_bounds__(128) void ln_kernel(
    float* __restrict__ io, const float* __restrict__ gamma,
    const float* __restrict__ beta)
{
    const int row = blockIdx.x, t = threadIdx.x;
    float* p = io + (size_t)row * EE;
    float4 v = reinterpret_cast<float4*>(p)[t];
    float s1 = v.x + v.y + v.z + v.w;
    float s2 = v.x * v.x + v.y * v.y + v.z * v.z + v.w * v.w;
#pragma unroll
    for (int o = 16; o > 0; o >>= 1) {
        s1 += __shfl_xor_sync(0xffffffffu, s1, o);
        s2 += __shfl_xor_sync(0xffffffffu, s2, o);
    }
    __shared__ float sh1[4], sh2[4];
    if ((t & 31) == 0) { sh1[t >> 5] = s1; sh2[t >> 5] = s2; }
    __syncthreads();
    s1 = sh1[0] + sh1[1] + sh1[2] + sh1[3];
    s2 = sh2[0] + sh2[1] + sh2[2] + sh2[3];
    const float mu = s1 * (1.0f / EE);
    const float inv = rsqrtf(s2 * (1.0f / EE) - mu * mu + 1e-5f);
    const float4 ga = reinterpret_cast<const float4*>(gamma)[t];
    const float4 be = reinterpret_cast<const float4*>(beta)[t];
    float4 o;
    o.x = (v.x - mu) * inv * ga.x + be.x;
    o.y = (v.y - mu) * inv * ga.y + be.y;
    o.z = (v.z - mu) * inv * ga.z + be.z;
    o.w = (v.w - mu) * inv * ga.w + be.w;
    reinterpret_cast<float4*>(p)[t] = o;
}

extern "C" void kernel_launch(void* const* d_in, const int* in_sizes, int n_in,
                              void* d_out, int out_size)
{
    const float* x  = (const float*)d_in[0];
    const float* W1 = (const float*)d_in[1];
    const float* b1 = (const float*)d_in[2];
    const float* W2 = (const float*)d_in[3];
    const float* b2 = (const float*)d_in[4];
    const float* ga = (const float*)d_in[5];
    const float* be = (const float*)d_in[6];
    float* out = (float*)d_out;

    static int init = 0;
    if (!init) {
        cudaFuncSetAttribute(ffn_mma<1>, cudaFuncAttributeMaxDynamicSharedMemorySize, SMB);
        cudaFuncSetAttribute(ffn_mma<2>, cudaFuncAttributeMaxDynamicSharedMemorySize, SMB);
        cudaFuncSetAttribute(ffn_mma<1>, cudaFuncAttributePreferredSharedMemoryCarveout, 100);
        cudaFuncSetAttribute(ffn_mma<2>, cudaFuncAttributePreferredSharedMemoryCarveout, 100);
        init = 1;
    }

    prepass<<<(BB * SQ * EE / 4) / 256, 256>>>(x);
    ffn_mma<1><<<dim3(FF / 256, SQ), 256, SMB>>>(W1, b1, nullptr, nullptr);
    ffn_mma<2><<<dim3(EE / 256, SQ), 256, SMB>>>(W2, b2, x, out);
    ln_kernel<<<BB * SQ, 128>>>(out, ga, be);
}

// round 10
// speedup vs baseline: 3.8832x; 1.0018x over previous
#include <cuda_runtime.h>
#include <cstdint>

#define BB 32
#define SQ 128
#define EE 512
#define FF 2048

__device__ float g_H[(size_t)SQ * BB * FF];  // [s][b][f]

#define STG1 18944            // A 32x80=2560 + B 16x1024=16384
#define SMB1 (4 * STG1)
#define STG2 35328            // A 32x80=2560 + B 16x2048=32768
#define SMB2 (4 * STG2)

__device__ __forceinline__ uint32_t smem_u32(const void* p) {
    uint32_t a;
    asm("{ .reg .u64 t; cvta.to.shared.u64 t, %1; cvt.u32.u64 %0, t; }" : "=r"(a) : "l"(p));
    return a;
}
__device__ __forceinline__ float rna(float v) {
    uint32_t r;
    asm("cvt.rna.tf32.f32 %0, %1;" : "=r"(r) : "f"(v));
    return __uint_as_float(r);
}
__device__ __forceinline__ uint32_t lds32(uint32_t a) {
    uint32_t v;
    asm volatile("ld.shared.b32 %0, [%1];" : "=r"(v) : "r"(a));
    return v;
}
__device__ __forceinline__ void cpa16(uint32_t dst, const void* src) {
    asm volatile("cp.async.cg.shared.global [%0], [%1], 16;" :: "r"(dst), "l"(src) : "memory");
}
__device__ __forceinline__ void cpa_commit() {
    asm volatile("cp.async.commit_group;" ::: "memory");
}
__device__ __forceinline__ void cpa_wait2() {
    asm volatile("cp.async.wait_group 2;" ::: "memory");
}
__device__ __forceinline__ void mma8(float* c, const uint32_t* a, const uint32_t* b) {
    asm volatile(
        "mma.sync.aligned.m16n8k8.row.col.f32.tf32.tf32.f32 "
        "{%0,%1,%2,%3}, {%4,%5,%6,%7}, {%8,%9}, {%0,%1,%2,%3};"
        : "+f"(c[0]), "+f"(c[1]), "+f"(c[2]), "+f"(c[3])
        : "r"(a[0]), "r"(a[1]), "r"(a[2]), "r"(a[3]), "r"(b[0]), "r"(b[1]));
}

// ---------------- GEMM1: H[s][b][f] = rna(x[:,s,:]) @ W1[s] + b1[s] ----------------
__global__ __launch_bounds__(256, 3) void ffn1(
    const float* __restrict__ W1, const float* __restrict__ b1,
    const float* __restrict__ x)
{
    constexpr int NCH = EE / 16;
    extern __shared__ char smem[];
    const uint32_t sb = smem_u32(smem);
    const int tid = threadIdx.x, wid = tid >> 5, lid = tid & 31;
    const int s = blockIdx.y, n0 = blockIdx.x * 256;
    const uint32_t g = lid >> 2, tig = lid & 3;

    const float* Ab = x + (size_t)s * EE;
    const float* Wb = W1 + (size_t)s * ((size_t)EE * FF) + n0;
    const int arow = tid >> 2, ac4 = tid & 3;
    const int br0 = tid >> 6, bc4 = tid & 63;

    auto issue = [&](int c) {
        const uint32_t stg = sb + (c & 3) * STG1;
        const int k0 = c * 16;
        if (tid < 128)
            cpa16(stg + arow * 80 + ac4 * 16,
                  Ab + (size_t)arow * SQ * EE + k0 + ac4 * 4);
#pragma unroll
        for (int i = 0; i < 4; i++) {
            const int r = br0 + i * 4;
            cpa16(stg + 2560 + r * 1024 + (((bc4 + 2 * (r & 3)) & 63) << 4),
                  Wb + (size_t)(k0 + r) * FF + bc4 * 4);
        }
        cpa_commit();
    };
    issue(0); issue(1); issue(2);

    float acc[2][4][4];
#pragma unroll
    for (int i = 0; i < 2; i++)
#pragma unroll
        for (int j = 0; j < 4; j++)
#pragma unroll
            for (int q = 0; q < 4; q++) acc[i][j][q] = 0.0f;

    uint32_t bcol[4];
#pragma unroll
    for (int nt = 0; nt < 4; nt++) {
        const uint32_t n = wid * 32 + nt * 8 + g;
        bcol[nt] = ((((n >> 2) + 2 * tig) & 63) << 4) + (n & 3) * 4;
    }

#pragma unroll 1
    for (int c = 0; c < NCH; c++) {
        cpa_wait2();
        __syncthreads();
        if (c + 3 < NCH) issue(c + 3); else cpa_commit();
        const uint32_t Aa = sb + (c & 3) * STG1;
        const uint32_t Ba = Aa + 2560;
#pragma unroll
        for (int ks = 0; ks < 2; ks++) {
            uint32_t a[2][4], b[4][2];
#pragma unroll
            for (int mt = 0; mt < 2; mt++) {
                const uint32_t base = Aa + (mt * 16 + g) * 80 + (ks * 8 + tig) * 4;
                a[mt][0] = lds32(base);
                a[mt][1] = lds32(base + 8 * 80);
                a[mt][2] = lds32(base + 16);
                a[mt][3] = lds32(base + 8 * 80 + 16);
#pragma unroll
                for (int q = 0; q < 4; q++)
                    a[mt][q] = __float_as_uint(rna(__uint_as_float(a[mt][q])));
            }
            const uint32_t kk = ks * 8 + tig;
#pragma unroll
            for (int nt = 0; nt < 4; nt++) {
                b[nt][0] = lds32(Ba + kk * 1024 + bcol[nt]);
                b[nt][1] = lds32(Ba + (kk + 4) * 1024 + bcol[nt]);
            }
#pragma unroll
            for (int mt = 0; mt < 2; mt++)
#pragma unroll
                for (int nt = 0; nt < 4; nt++) mma8(acc[mt][nt], a[mt], b[nt]);
        }
    }

#pragma unroll
    for (int mt = 0; mt < 2; mt++)
#pragma unroll
        for (int half = 0; half < 2; half++) {
            const int m = mt * 16 + g + half * 8;
#pragma unroll
            for (int nt = 0; nt < 4; nt++) {
                const int n = n0 + wid * 32 + nt * 8 + 2 * tig;
                const float b0 = b1[(size_t)s * FF + n];
                const float b1v = b1[(size_t)s * FF + n + 1];
                float2 o = make_float2(rna(acc[mt][nt][half * 2] + b0),
                                       rna(acc[mt][nt][half * 2 + 1] + b1v));
                *reinterpret_cast<float2*>(g_H + ((size_t)s * BB + m) * FF + n) = o;
            }
        }
}

// ------- GEMM2 + LN: out = LN(H[s] @ W2[s] + b2[s] + x), one block per s -------
__global__ __launch_bounds__(512, 1) void ffn2_ln(
    const float* __restrict__ W2, const float* __restrict__ b2,
    const float* __restrict__ x, const float* __restrict__ gamma,
    const float* __restrict__ beta, float* __restrict__ outp)
{
    constexpr int NCH = FF / 16;
    extern __shared__ char smem[];
    const uint32_t sb = smem_u32(smem);
    const int tid = threadIdx.x, wid = tid >> 5, lid = tid & 31;
    const int s = blockIdx.x;
    const uint32_t g = lid >> 2, tig = lid & 3;

    const float* Ab = g_H + (size_t)s * BB * FF;
    const float* Wb = W2 + (size_t)s * ((size_t)FF * EE);
    const int arow = tid >> 2, ac4 = tid & 3;
    const int br0 = tid >> 7, bc4 = tid & 127;

    auto issue = [&](int c) {
        const uint32_t stg = sb + (c & 3) * STG2;
        const int k0 = c * 16;
        if (tid < 128)
            cpa16(stg + arow * 80 + ac4 * 16, Ab + (size_t)arow * FF + k0 + ac4 * 4);
#pragma unroll
        for (int i = 0; i < 4; i++) {
            const int r = br0 + i * 4;
            cpa16(stg + 2560 + r * 2048 + (((bc4 + 2 * (r & 3)) & 127) << 4),
                  Wb + (size_t)(k0 + r) * EE + bc4 * 4);
        }
        cpa_commit();
    };
    issue(0); issue(1); issue(2);

    float acc[2][4][4];
#pragma unroll
    for (int i = 0; i < 2; i++)
#pragma unroll
        for (int j = 0; j < 4; j++)
#pragma unroll
            for (int q = 0; q < 4; q++) acc[i][j][q] = 0.0f;

    uint32_t bcol[4];
#pragma unroll
    for (int nt = 0; nt < 4; nt++) {
        const uint32_t n = wid * 32 + nt * 8 + g;
        bcol[nt] = ((((n >> 2) + 2 * tig) & 127) << 4) + (n & 3) * 4;
    }

#pragma unroll 1
    for (int c = 0; c < NCH; c++) {
        cpa_wait2();
        __syncthreads();
        if (c + 3 < NCH) issue(c + 3); else cpa_commit();
        const uint32_t Aa = sb + (c & 3) * STG2;
        const uint32_t Ba = Aa + 2560;
#pragma unroll
        for (int ks = 0; ks < 2; ks++) {
            uint32_t a[2][4], b[4][2];
#pragma unroll
            for (int mt = 0; mt < 2; mt++) {
                const uint32_t base = Aa + (mt * 16 + g) * 80 + (ks * 8 + tig) * 4;
                a[mt][0] = lds32(base);
                a[mt][1] = lds32(base + 8 * 80);
                a[mt][2] = lds32(base + 16);
                a[mt][3] = lds32(base + 8 * 80 + 16);
            }
            const uint32_t kk = ks * 8 + tig;
#pragma unroll
            for (int nt = 0; nt < 4; nt++) {
                b[nt][0] = lds32(Ba + kk * 2048 + bcol[nt]);
                b[nt][1] = lds32(Ba + (kk + 4) * 2048 + bcol[nt]);
            }
#pragma unroll
            for (int mt = 0; mt < 2; mt++)
#pragma unroll
                for (int nt = 0; nt < 4; nt++) mma8(acc[mt][nt], a[mt], b[nt]);
        }
    }

    // y = acc + b2 + x  (in-register), then block LN over e (512)
#pragma unroll
    for (int mt = 0; mt < 2; mt++)
#pragma unroll
        for (int half = 0; half < 2; half++) {
            const int m = mt * 16 + g + half * 8;
#pragma unroll
            for (int nt = 0; nt < 4; nt++) {
                const int n = wid * 32 + nt * 8 + 2 * tig;
                const float2 xr = *reinterpret_cast<const float2*>(
                    x + ((size_t)m * SQ + s) * EE + n);
                acc[mt][nt][half * 2]     += b2[(size_t)s * EE + n] + xr.x;
                acc[mt][nt][half * 2 + 1] += b2[(size_t)s * EE + n + 1] + xr.y;
            }
        }

    float* redS = reinterpret_cast<float*>(smem);           // [16][32]
    float* redQ = redS + 512;                               // [16][32]
    float* muS  = redQ + 512;                               // [32]
    float* invS = muS + 32;                                 // [32]
    __syncthreads();
#pragma unroll
    for (int mt = 0; mt < 2; mt++)
#pragma unroll
        for (int half = 0; half < 2; half++) {
            float s1 = 0.f, s2 = 0.f;
#pragma unroll
            for (int nt = 0; nt < 4; nt++) {
                const float v0 = acc[mt][nt][half * 2], v1 = acc[mt][nt][half * 2 + 1];
                s1 += v0 + v1;
                s2 += v0 * v0 + v1 * v1;
            }
            s1 += __shfl_xor_sync(0xffffffffu, s1, 1);
            s1 += __shfl_xor_sync(0xffffffffu, s1, 2);
            s2 += __shfl_xor_sync(0xffffffffu, s2, 1);
            s2 += __shfl_xor_sync(0xffffffffu, s2, 2);
            if (tig == 0) {
                const int m = mt * 16 + half * 8 + g;
                redS[wid * 32 + m] = s1;
                redQ[wid * 32 + m] = s2;
            }
        }
    __syncthreads();
    if (tid < 32) {
        float s1 = 0.f, s2 = 0.f;
#pragma unroll
        for (int w = 0; w < 16; w++) { s1 += redS[w * 32 + tid]; s2 += redQ[w * 32 + tid]; }
        const float mu = s1 * (1.0f / EE);
        muS[tid]  = mu;
        invS[tid] = rsqrtf(s2 * (1.0f / EE) - mu * mu + 1e-5f);
    }
    __syncthreads();
#pragma unroll
    for (int mt = 0; mt < 2; mt++)
#pragma unroll
        for (int half = 0; half < 2; half++) {
            const int m = mt * 16 + g + half * 8;
            const float mu = muS[m], inv = invS[m];
#pragma unroll
            for (int nt = 0; nt < 4; nt++) {
                const int n = wid * 32 + nt * 8 + 2 * tig;
                const float2 ga = *reinterpret_cast<const float2*>(gamma + n);
                const float2 be = *reinterpret_cast<const float2*>(beta + n);
                float2 o;
                o.x = (acc[mt][nt][half * 2]     - mu) * inv * ga.x + be.x;
                o.y = (acc[mt][nt][half * 2 + 1] - mu) * inv * ga.y + be.y;
                *reinterpret_cast<float2*>(outp + ((size_t)m * SQ + s) * EE + n) = o;
            }
        }
}

extern "C" void kernel_launch(void* const* d_in, const int* in_sizes, int n_in,
                              void* d_out, int out_size)
{
    const float* x  = (const float*)d_in[0];
    const float* W1 = (const float*)d_in[1];
    const float* b1 = (const float*)d_in[2];
    const float* W2 = (const float*)d_in[3];
    const float* b2 = (const float*)d_in[4];
    const float* ga = (const float*)d_in[5];
    const float* be = (const float*)d_in[6];
    float* out = (float*)d_out;

    static int init = 0;
    if (!init) {
        cudaFuncSetAttribute(ffn1, cudaFuncAttributeMaxDynamicSharedMemorySize, SMB1);
        cudaFuncSetAttribute(ffn2_ln, cudaFuncAttributeMaxDynamicSharedMemorySize, SMB2);
        cudaFuncSetAttribute(ffn1, cudaFuncAttributePreferredSharedMemoryCarveout, 100);
        cudaFuncSetAttribute(ffn2_ln, cudaFuncAttributePreferredSharedMemoryCarveout, 100);
        init = 1;
    }

    ffn1<<<dim3(FF / 256, SQ), 256, SMB1>>>(W1, b1, x);
    ffn2_ln<<<SQ, 512, SMB2>>>(W2, b2, x, ga, be, out);
}